// round 2
// baseline (speedup 1.0000x reference)
#include <cuda_runtime.h>

#define DOUT 128
#define N_MAX 50000
#define E_MAX 800000

// Scratch (device globals — no allocation allowed)
__device__ float g_z[(size_t)N_MAX * DOUT];
__device__ float g_ssrc[N_MAX];
__device__ float g_sdst[N_MAX];
__device__ int   g_cnt[N_MAX];
__device__ int   g_off[N_MAX + 1];
__device__ int   g_cur[N_MAX];
__device__ int   g_packed[E_MAX];   // src | (etype << 17)

// ---------------------------------------------------------------------------
__global__ void clear_cnt(int N) {
    int i = blockIdx.x * blockDim.x + threadIdx.x;
    if (i < N) g_cnt[i] = 0;
}

// ---------------------------------------------------------------------------
// z = h @ W  (smem-tiled fp32), plus s_src = z@a_l, s_dst = z@a_r
// ---------------------------------------------------------------------------
__global__ void __launch_bounds__(256, 2)
gemm_kernel(const float* __restrict__ h, const float* __restrict__ W,
            const float* __restrict__ attn, int N) {
    extern __shared__ float smem[];
    float* Ws = smem;                 // [128][128]
    float* hs = smem + DOUT * DOUT;   // [64][128]

    int tid = threadIdx.x;
    const float4* W4 = (const float4*)W;
    float4* Ws4 = (float4*)Ws;
#pragma unroll
    for (int i = 0; i < 16; i++)
        Ws4[tid + i * 256] = W4[tid + i * 256];

    int rowbase = blockIdx.x * 64;
    float4* hs4 = (float4*)hs;
    const float4* h4 = (const float4*)h;
#pragma unroll
    for (int i = 0; i < 8; i++) {
        int idx = tid + i * 256;
        int r = idx >> 5;
        int c = idx & 31;
        float4 v = make_float4(0.f, 0.f, 0.f, 0.f);
        if (rowbase + r < N) v = h4[(size_t)(rowbase + r) * 32 + c];
        hs4[idx] = v;
    }
    __syncthreads();

    int warp = tid >> 5, lane = tid & 31;
    int r0 = warp * 8;

    float4 acc[8];
#pragma unroll
    for (int r = 0; r < 8; r++) acc[r] = make_float4(0.f, 0.f, 0.f, 0.f);

#pragma unroll 4
    for (int k = 0; k < DOUT; k++) {
        float4 wk = Ws4[k * 32 + lane];
#pragma unroll
        for (int r = 0; r < 8; r++) {
            float hv = hs[(r0 + r) * DOUT + k];
            acc[r].x += hv * wk.x;
            acc[r].y += hv * wk.y;
            acc[r].z += hv * wk.z;
            acc[r].w += hv * wk.w;
        }
    }

    float4 al = ((const float4*)attn)[lane];
    float4 ar = ((const float4*)attn)[32 + lane];
    float4* z4 = (float4*)g_z;
#pragma unroll
    for (int r = 0; r < 8; r++) {
        int row = rowbase + r0 + r;
        if (row >= N) break;
        z4[(size_t)row * 32 + lane] = acc[r];
        float ps = acc[r].x * al.x + acc[r].y * al.y + acc[r].z * al.z + acc[r].w * al.w;
        float pd = acc[r].x * ar.x + acc[r].y * ar.y + acc[r].z * ar.z + acc[r].w * ar.w;
#pragma unroll
        for (int o = 16; o > 0; o >>= 1) {
            ps += __shfl_xor_sync(0xffffffffu, ps, o);
            pd += __shfl_xor_sync(0xffffffffu, pd, o);
        }
        if (lane == 0) { g_ssrc[row] = ps; g_sdst[row] = pd; }
    }
}

// ---------------------------------------------------------------------------
// CSR build: histogram of dst, single-block scan, atomic-cursor scatter
// ---------------------------------------------------------------------------
__global__ void hist_kernel(const int* __restrict__ dst, int E) {
    int i = blockIdx.x * blockDim.x + threadIdx.x;
    if (i < E) atomicAdd(&g_cnt[dst[i]], 1);
}

__global__ void __launch_bounds__(1024, 1)
scan_kernel(int N) {
    __shared__ int wsum[32];
    int lane = threadIdx.x & 31, wid = threadIdx.x >> 5;
    int carry = 0;
    for (int base = 0; base < N; base += 1024) {
        int i = base + threadIdx.x;
        int v = (i < N) ? g_cnt[i] : 0;
        int x = v;
#pragma unroll
        for (int o = 1; o < 32; o <<= 1) {
            int y = __shfl_up_sync(0xffffffffu, x, o);
            if (lane >= o) x += y;
        }
        if (lane == 31) wsum[wid] = x;
        __syncthreads();
        if (wid == 0) {
            int s = wsum[lane];
#pragma unroll
            for (int o = 1; o < 32; o <<= 1) {
                int y = __shfl_up_sync(0xffffffffu, s, o);
                if (lane >= o) s += y;
            }
            wsum[lane] = s;
        }
        __syncthreads();
        int warp_excl = (wid == 0) ? 0 : wsum[wid - 1];
        int excl = carry + warp_excl + x - v;
        if (i < N) { g_off[i] = excl; g_cur[i] = excl; }
        carry += wsum[31];
        __syncthreads();
    }
    if (threadIdx.x == 0) g_off[N] = carry;
}

__global__ void scatter_kernel(const int* __restrict__ src, const int* __restrict__ dst,
                               const int* __restrict__ etype, int E) {
    int i = blockIdx.x * blockDim.x + threadIdx.x;
    if (i >= E) return;
    int d = dst[i];
    int pos = atomicAdd(&g_cur[d], 1);
    g_packed[pos] = src[i] | (etype[i] << 17);
}

// ---------------------------------------------------------------------------
// One warp per dst node: fused softmax (no max needed — scores bounded,
// leaky_relu monotone) + weighted z gather + normalize. No float atomics.
// ---------------------------------------------------------------------------
__global__ void __launch_bounds__(256)
gather_kernel(const float* __restrict__ rel, float* __restrict__ out, int N) {
    int node = (blockIdx.x * blockDim.x + threadIdx.x) >> 5;
    int lane = threadIdx.x & 31;
    if (node >= N) return;

    int beg = g_off[node], end = g_off[node + 1];
    float sd = g_sdst[node];

    float4 acc = make_float4(0.f, 0.f, 0.f, 0.f);
    float dsum = 0.f;
    const float4* z4 = (const float4*)g_z;

    for (int base = beg; base < end; base += 32) {
        int idx = base + lane;
        float w = 0.f, exv = 0.f;
        int s = 0;
        if (idx < end) {
            int p = g_packed[idx];
            s = p & 131071;
            int et = p >> 17;
            float v = g_ssrc[s] + sd;
            float e = v > 0.f ? v : 0.01f * v;
            exv = __expf(e);
            w = (et == 0 ? 0.f : __ldg(&rel[et])) * exv;
        }
        dsum += exv;
        int cnt = min(32, end - base);
#pragma unroll 4
        for (int i = 0; i < cnt; i++) {
            float wi = __shfl_sync(0xffffffffu, w, i);
            int   si = __shfl_sync(0xffffffffu, s, i);
            float4 zv = z4[(size_t)si * 32 + lane];
            acc.x += wi * zv.x;
            acc.y += wi * zv.y;
            acc.z += wi * zv.z;
            acc.w += wi * zv.w;
        }
    }

#pragma unroll
    for (int o = 16; o > 0; o >>= 1)
        dsum += __shfl_xor_sync(0xffffffffu, dsum, o);

    float inv = dsum > 0.f ? __frcp_rn(dsum) : 0.f;
    float4* o4 = (float4*)out;
    o4[(size_t)node * 32 + lane] =
        make_float4(acc.x * inv, acc.y * inv, acc.z * inv, acc.w * inv);
}

// ---------------------------------------------------------------------------
extern "C" void kernel_launch(void* const* d_in, const int* in_sizes, int n_in,
                              void* d_out, int out_size) {
    const float* h    = (const float*)d_in[0];
    const float* W    = (const float*)d_in[1];
    const float* attn = (const float*)d_in[2];
    const float* rel  = (const float*)d_in[3];
    const int*   src  = (const int*)d_in[4];
    const int*   dst  = (const int*)d_in[5];
    const int*   et   = (const int*)d_in[6];
    float* out = (float*)d_out;

    int N = in_sizes[0] / DOUT;
    int E = in_sizes[4];

    clear_cnt<<<(N + 255) / 256, 256>>>(N);

    cudaFuncSetAttribute(gemm_kernel, cudaFuncAttributeMaxDynamicSharedMemorySize, 96 * 1024);
    gemm_kernel<<<(N + 63) / 64, 256, 96 * 1024>>>(h, W, attn, N);

    hist_kernel<<<(E + 255) / 256, 256>>>(dst, E);
    scan_kernel<<<1, 1024>>>(N);
    scatter_kernel<<<(E + 255) / 256, 256>>>(src, dst, et, E);

    gather_kernel<<<(N * 32 + 255) / 256, 256>>>(rel, out, N);
}

// round 3
// speedup vs baseline: 1.2534x; 1.2534x over previous
#include <cuda_runtime.h>

#define DOUT 128
#define N_MAX 50000
#define E_MAX 800000
#define SCAN_CHUNK 2048

// Scratch (device globals — no allocation allowed)
__device__ float g_z[(size_t)N_MAX * DOUT];
__device__ float g_ssrc[N_MAX];
__device__ float g_sdst[N_MAX];
__device__ int   g_cnt[N_MAX];
__device__ int   g_off[N_MAX + 1];
__device__ int   g_cur[N_MAX];
__device__ int   g_packed[E_MAX];   // src | (etype << 17)
__device__ int   g_part[1024];
__device__ int   g_partoff[1024];

// ---------------------------------------------------------------------------
__global__ void clear_cnt(int N) {
    int i = blockIdx.x * blockDim.x + threadIdx.x;
    if (i < N) g_cnt[i] = 0;
}

// ---------------------------------------------------------------------------
// z = h @ W  (smem-tiled fp32), plus s_src = z@a_l, s_dst = z@a_r
// ---------------------------------------------------------------------------
__global__ void __launch_bounds__(256, 2)
gemm_kernel(const float* __restrict__ h, const float* __restrict__ W,
            const float* __restrict__ attn, int N) {
    extern __shared__ float smem[];
    float* Ws = smem;                 // [128][128]
    float* hs = smem + DOUT * DOUT;   // [64][128]

    int tid = threadIdx.x;
    const float4* W4 = (const float4*)W;
    float4* Ws4 = (float4*)Ws;
#pragma unroll
    for (int i = 0; i < 16; i++)
        Ws4[tid + i * 256] = W4[tid + i * 256];

    int rowbase = blockIdx.x * 64;
    float4* hs4 = (float4*)hs;
    const float4* h4 = (const float4*)h;
#pragma unroll
    for (int i = 0; i < 8; i++) {
        int idx = tid + i * 256;
        int r = idx >> 5;
        int c = idx & 31;
        float4 v = make_float4(0.f, 0.f, 0.f, 0.f);
        if (rowbase + r < N) v = h4[(size_t)(rowbase + r) * 32 + c];
        hs4[idx] = v;
    }
    __syncthreads();

    int warp = tid >> 5, lane = tid & 31;
    int r0 = warp * 8;

    float4 acc[8];
#pragma unroll
    for (int r = 0; r < 8; r++) acc[r] = make_float4(0.f, 0.f, 0.f, 0.f);

#pragma unroll 4
    for (int k = 0; k < DOUT; k++) {
        float4 wk = Ws4[k * 32 + lane];
#pragma unroll
        for (int r = 0; r < 8; r++) {
            float hv = hs[(r0 + r) * DOUT + k];
            acc[r].x += hv * wk.x;
            acc[r].y += hv * wk.y;
            acc[r].z += hv * wk.z;
            acc[r].w += hv * wk.w;
        }
    }

    float4 al = ((const float4*)attn)[lane];
    float4 ar = ((const float4*)attn)[32 + lane];
    float4* z4 = (float4*)g_z;
#pragma unroll
    for (int r = 0; r < 8; r++) {
        int row = rowbase + r0 + r;
        if (row >= N) break;
        z4[(size_t)row * 32 + lane] = acc[r];
        float ps = acc[r].x * al.x + acc[r].y * al.y + acc[r].z * al.z + acc[r].w * al.w;
        float pd = acc[r].x * ar.x + acc[r].y * ar.y + acc[r].z * ar.z + acc[r].w * ar.w;
#pragma unroll
        for (int o = 16; o > 0; o >>= 1) {
            ps += __shfl_xor_sync(0xffffffffu, ps, o);
            pd += __shfl_xor_sync(0xffffffffu, pd, o);
        }
        if (lane == 0) { g_ssrc[row] = ps; g_sdst[row] = pd; }
    }
}

// ---------------------------------------------------------------------------
// CSR build: histogram, 3-stage multi-block scan, atomic-cursor scatter
// ---------------------------------------------------------------------------
__global__ void hist_kernel(const int* __restrict__ dst, int E) {
    int i = blockIdx.x * blockDim.x + threadIdx.x;
    if (i < E) atomicAdd(&g_cnt[dst[i]], 1);
}

// Stage A: per-chunk sums (256 threads per block, chunk = 2048 counts)
__global__ void scan_reduce(int N) {
    __shared__ int ws[8];
    int b = blockIdx.x, t = threadIdx.x;
    int base = b * SCAN_CHUNK;
    int sum = 0;
#pragma unroll
    for (int i = t; i < SCAN_CHUNK; i += 256) {
        int idx = base + i;
        if (idx < N) sum += g_cnt[idx];
    }
    int lane = t & 31, wid = t >> 5;
#pragma unroll
    for (int o = 16; o > 0; o >>= 1) sum += __shfl_xor_sync(0xffffffffu, sum, o);
    if (lane == 0) ws[wid] = sum;
    __syncthreads();
    if (t == 0) {
        int s = 0;
#pragma unroll
        for (int i = 0; i < 8; i++) s += ws[i];
        g_part[b] = s;
    }
}

// Stage B: exclusive scan of nblk (<=1024) partials in one block; writes g_off[N]
__global__ void __launch_bounds__(1024, 1)
scan_part(int nblk, int N) {
    __shared__ int wsum[32];
    int t = threadIdx.x, lane = t & 31, wid = t >> 5;
    int v = (t < nblk) ? g_part[t] : 0;
    int x = v;
#pragma unroll
    for (int o = 1; o < 32; o <<= 1) {
        int y = __shfl_up_sync(0xffffffffu, x, o);
        if (lane >= o) x += y;
    }
    if (lane == 31) wsum[wid] = x;
    __syncthreads();
    if (wid == 0) {
        int s = wsum[lane];
#pragma unroll
        for (int o = 1; o < 32; o <<= 1) {
            int y = __shfl_up_sync(0xffffffffu, s, o);
            if (lane >= o) s += y;
        }
        wsum[lane] = s;
    }
    __syncthreads();
    int excl = (wid == 0 ? 0 : wsum[wid - 1]) + x - v;
    if (t < nblk) g_partoff[t] = excl;
    if (t == 0) g_off[N] = wsum[31];
}

// Stage C: per-chunk exclusive scan with carry; fills g_off and g_cur
__global__ void __launch_bounds__(256)
scan_final(int N) {
    __shared__ int ws[8];
    int b = blockIdx.x, t = threadIdx.x;
    int base = b * SCAN_CHUNK + t * 8;   // thread owns 8 contiguous counts
    int lane = t & 31, wid = t >> 5;

    int vals[8];
    int tsum = 0;
#pragma unroll
    for (int j = 0; j < 8; j++) {
        int idx = base + j;
        vals[j] = (idx < N) ? g_cnt[idx] : 0;
        tsum += vals[j];
    }
    int x = tsum;
#pragma unroll
    for (int o = 1; o < 32; o <<= 1) {
        int y = __shfl_up_sync(0xffffffffu, x, o);
        if (lane >= o) x += y;
    }
    if (lane == 31) ws[wid] = x;
    __syncthreads();
    if (t < 8) {
        int s = ws[t];
#pragma unroll
        for (int o = 1; o < 8; o <<= 1) {
            int y = __shfl_up_sync(0x000000ffu, s, o);
            if ((t & 7) >= o) s += y;
        }
        ws[t] = s;
    }
    __syncthreads();
    int run = g_partoff[b] + (wid == 0 ? 0 : ws[wid - 1]) + x - tsum;
#pragma unroll
    for (int j = 0; j < 8; j++) {
        int idx = base + j;
        if (idx < N) { g_off[idx] = run; g_cur[idx] = run; }
        run += vals[j];
    }
}

__global__ void scatter_kernel(const int* __restrict__ src, const int* __restrict__ dst,
                               const int* __restrict__ etype, int E) {
    int i = blockIdx.x * blockDim.x + threadIdx.x;
    if (i >= E) return;
    int d = dst[i];
    int pos = atomicAdd(&g_cur[d], 1);
    g_packed[pos] = src[i] | (etype[i] << 17);
}

// ---------------------------------------------------------------------------
// One warp per dst node: fused softmax (no max shift needed — scores bounded,
// leaky_relu monotone) + weighted z gather + normalize. No float atomics.
// ---------------------------------------------------------------------------
__global__ void __launch_bounds__(256)
gather_kernel(const float* __restrict__ rel, float* __restrict__ out, int N) {
    int node = (blockIdx.x * blockDim.x + threadIdx.x) >> 5;
    int lane = threadIdx.x & 31;
    if (node >= N) return;

    int beg = g_off[node], end = g_off[node + 1];
    float sd = g_sdst[node];

    float4 acc = make_float4(0.f, 0.f, 0.f, 0.f);
    float dsum = 0.f;
    const float4* z4 = (const float4*)g_z;

    for (int base = beg; base < end; base += 32) {
        int idx = base + lane;
        float w = 0.f, exv = 0.f;
        int s = 0;
        if (idx < end) {
            int p = g_packed[idx];
            s = p & 131071;
            int et = p >> 17;
            float v = g_ssrc[s] + sd;
            float e = v > 0.f ? v : 0.01f * v;
            exv = __expf(e);
            w = (et == 0 ? 0.f : __ldg(&rel[et])) * exv;
        }
        dsum += exv;
        int cnt = min(32, end - base);
#pragma unroll 4
        for (int i = 0; i < cnt; i++) {
            float wi = __shfl_sync(0xffffffffu, w, i);
            int   si = __shfl_sync(0xffffffffu, s, i);
            float4 zv = z4[(size_t)si * 32 + lane];
            acc.x += wi * zv.x;
            acc.y += wi * zv.y;
            acc.z += wi * zv.z;
            acc.w += wi * zv.w;
        }
    }

#pragma unroll
    for (int o = 16; o > 0; o >>= 1)
        dsum += __shfl_xor_sync(0xffffffffu, dsum, o);

    float inv = dsum > 0.f ? __frcp_rn(dsum) : 0.f;
    float4* o4 = (float4*)out;
    o4[(size_t)node * 32 + lane] =
        make_float4(acc.x * inv, acc.y * inv, acc.z * inv, acc.w * inv);
}

// ---------------------------------------------------------------------------
extern "C" void kernel_launch(void* const* d_in, const int* in_sizes, int n_in,
                              void* d_out, int out_size) {
    const float* h    = (const float*)d_in[0];
    const float* W    = (const float*)d_in[1];
    const float* attn = (const float*)d_in[2];
    const float* rel  = (const float*)d_in[3];
    const int*   src  = (const int*)d_in[4];
    const int*   dst  = (const int*)d_in[5];
    const int*   et   = (const int*)d_in[6];
    float* out = (float*)d_out;

    int N = in_sizes[0] / DOUT;
    int E = in_sizes[4];
    int nblk = (N + SCAN_CHUNK - 1) / SCAN_CHUNK;

    clear_cnt<<<(N + 255) / 256, 256>>>(N);

    cudaFuncSetAttribute(gemm_kernel, cudaFuncAttributeMaxDynamicSharedMemorySize, 96 * 1024);
    gemm_kernel<<<(N + 63) / 64, 256, 96 * 1024>>>(h, W, attn, N);

    hist_kernel<<<(E + 255) / 256, 256>>>(dst, E);
    scan_reduce<<<nblk, 256>>>(N);
    scan_part<<<1, 1024>>>(nblk, N);
    scan_final<<<nblk, 256>>>(N);
    scatter_kernel<<<(E + 255) / 256, 256>>>(src, dst, et, E);

    gather_kernel<<<(N * 32 + 255) / 256, 256>>>(rel, out, N);
}

// round 4
// speedup vs baseline: 1.8361x; 1.4649x over previous
#include <cuda_runtime.h>

#define DOUT 128
#define N_MAX 50000
#define E_MAX 800000
#define CHUNK 4096

// Scratch (device globals — no allocation allowed)
__device__ float g_z[(size_t)N_MAX * DOUT];
__device__ float g_ssrc[N_MAX];
__device__ float g_sdst[N_MAX];
__device__ int   g_cnt[N_MAX];
__device__ int   g_off[N_MAX + 1];
__device__ int   g_cur[N_MAX];
__device__ int   g_packed[E_MAX];   // src | (etype << 17)

// ---------------------------------------------------------------------------
// z = h @ W  (smem-tiled fp32), plus s_src = z@a_l, s_dst = z@a_r.
// Also zeroes g_cnt as a side job (stream order puts hist after us).
// ---------------------------------------------------------------------------
__global__ void __launch_bounds__(256, 2)
gemm_kernel(const float* __restrict__ h, const float* __restrict__ W,
            const float* __restrict__ attn, int N) {
    extern __shared__ float smem[];
    float* Ws = smem;                 // [128][128]
    float* hs = smem + DOUT * DOUT;   // [64][128]

    int tid = threadIdx.x;

    // fused clear of g_cnt (grid*256 >= N)
    int ci = blockIdx.x * 256 + tid;
    if (ci < N) g_cnt[ci] = 0;

    const float4* W4 = (const float4*)W;
    float4* Ws4 = (float4*)Ws;
#pragma unroll
    for (int i = 0; i < 16; i++)
        Ws4[tid + i * 256] = W4[tid + i * 256];

    int rowbase = blockIdx.x * 64;
    float4* hs4 = (float4*)hs;
    const float4* h4 = (const float4*)h;
#pragma unroll
    for (int i = 0; i < 8; i++) {
        int idx = tid + i * 256;
        int r = idx >> 5;
        int c = idx & 31;
        float4 v = make_float4(0.f, 0.f, 0.f, 0.f);
        if (rowbase + r < N) v = h4[(size_t)(rowbase + r) * 32 + c];
        hs4[idx] = v;
    }
    __syncthreads();

    int warp = tid >> 5, lane = tid & 31;
    int r0 = warp * 8;

    float4 acc[8];
#pragma unroll
    for (int r = 0; r < 8; r++) acc[r] = make_float4(0.f, 0.f, 0.f, 0.f);

#pragma unroll 4
    for (int k = 0; k < DOUT; k++) {
        float4 wk = Ws4[k * 32 + lane];
#pragma unroll
        for (int r = 0; r < 8; r++) {
            float hv = hs[(r0 + r) * DOUT + k];
            acc[r].x += hv * wk.x;
            acc[r].y += hv * wk.y;
            acc[r].z += hv * wk.z;
            acc[r].w += hv * wk.w;
        }
    }

    float4 al = ((const float4*)attn)[lane];
    float4 ar = ((const float4*)attn)[32 + lane];
    float4* z4 = (float4*)g_z;
#pragma unroll
    for (int r = 0; r < 8; r++) {
        int row = rowbase + r0 + r;
        if (row >= N) break;
        z4[(size_t)row * 32 + lane] = acc[r];
        float ps = acc[r].x * al.x + acc[r].y * al.y + acc[r].z * al.z + acc[r].w * al.w;
        float pd = acc[r].x * ar.x + acc[r].y * ar.y + acc[r].z * ar.z + acc[r].w * ar.w;
#pragma unroll
        for (int o = 16; o > 0; o >>= 1) {
            ps += __shfl_xor_sync(0xffffffffu, ps, o);
            pd += __shfl_xor_sync(0xffffffffu, pd, o);
        }
        if (lane == 0) { g_ssrc[row] = ps; g_sdst[row] = pd; }
    }
}

// ---------------------------------------------------------------------------
__global__ void hist_kernel(const int* __restrict__ dst, int E) {
    int i = blockIdx.x * blockDim.x + threadIdx.x;
    if (i < E) atomicAdd(&g_cnt[dst[i]], 1);
}

// ---------------------------------------------------------------------------
// Single-kernel exclusive scan: block b redundantly reduces [0, b*CHUNK)
// (worst case 196KB — trivially parallel, no inter-block protocol, no
// persistent flags to reset), then scans its own CHUNK.
// ---------------------------------------------------------------------------
__global__ void __launch_bounds__(256)
scan_kernel(int N) {
    __shared__ int sh[9];
    int b = blockIdx.x, t = threadIdx.x;
    int lane = t & 31, wid = t >> 5;
    int base = b * CHUNK;

    // 1) total of preceding chunks (base is multiple of CHUNK -> int4 aligned)
    int pre = 0;
    const int4* c4 = (const int4*)g_cnt;
    for (int i = t; i * 4 < base; i += 256) {
        int4 v = c4[i];
        pre += v.x + v.y + v.z + v.w;
    }
#pragma unroll
    for (int o = 16; o > 0; o >>= 1) pre += __shfl_xor_sync(0xffffffffu, pre, o);
    if (lane == 0) sh[wid] = pre;
    __syncthreads();
    if (t == 0) {
        int s = 0;
#pragma unroll
        for (int i = 0; i < 8; i++) s += sh[i];
        sh[8] = s;
    }
    __syncthreads();
    int pretot = sh[8];
    __syncthreads();

    // 2) own-chunk scan, 16 contiguous counts per thread
    int tbase = base + t * 16;
    int vals[16];
    int tsum = 0;
    if (tbase + 16 <= N) {
#pragma unroll
        for (int j = 0; j < 16; j += 4) {
            int4 v = c4[(tbase + j) >> 2];
            vals[j] = v.x; vals[j+1] = v.y; vals[j+2] = v.z; vals[j+3] = v.w;
            tsum += v.x + v.y + v.z + v.w;
        }
    } else {
#pragma unroll
        for (int j = 0; j < 16; j++) {
            int idx = tbase + j;
            vals[j] = (idx < N) ? g_cnt[idx] : 0;
            tsum += vals[j];
        }
    }

    int x = tsum;
#pragma unroll
    for (int o = 1; o < 32; o <<= 1) {
        int y = __shfl_up_sync(0xffffffffu, x, o);
        if (lane >= o) x += y;
    }
    if (lane == 31) sh[wid] = x;
    __syncthreads();
    if (t < 8) {
        int s = sh[t];
#pragma unroll
        for (int o = 1; o < 8; o <<= 1) {
            int y = __shfl_up_sync(0x000000ffu, s, o);
            if (t >= o) s += y;
        }
        sh[t] = s;
    }
    __syncthreads();

    int run = pretot + (wid ? sh[wid - 1] : 0) + x - tsum;
#pragma unroll
    for (int j = 0; j < 16; j++) {
        int idx = tbase + j;
        if (idx < N) { g_off[idx] = run; g_cur[idx] = run; }
        run += vals[j];
    }
    if (t == 0 && b == gridDim.x - 1) g_off[N] = pretot + sh[7];
}

// ---------------------------------------------------------------------------
__global__ void scatter_kernel(const int* __restrict__ src, const int* __restrict__ dst,
                               const int* __restrict__ etype, int E) {
    int i = blockIdx.x * blockDim.x + threadIdx.x;
    if (i >= E) return;
    int d = dst[i];
    int pos = atomicAdd(&g_cur[d], 1);
    g_packed[pos] = src[i] | (etype[i] << 17);
}

// ---------------------------------------------------------------------------
// One warp per dst node: fused softmax (no max shift needed — scores bounded,
// leaky_relu monotone) + weighted z gather + normalize. No float atomics.
// ---------------------------------------------------------------------------
__global__ void __launch_bounds__(256)
gather_kernel(const float* __restrict__ rel, float* __restrict__ out, int N) {
    int node = (blockIdx.x * blockDim.x + threadIdx.x) >> 5;
    int lane = threadIdx.x & 31;
    if (node >= N) return;

    int beg = g_off[node], end = g_off[node + 1];
    float sd = g_sdst[node];

    float4 acc = make_float4(0.f, 0.f, 0.f, 0.f);
    float dsum = 0.f;
    const float4* z4 = (const float4*)g_z;

    for (int base = beg; base < end; base += 32) {
        int idx = base + lane;
        float w = 0.f, exv = 0.f;
        int s = 0;
        if (idx < end) {
            int p = g_packed[idx];
            s = p & 131071;
            int et = p >> 17;
            float v = g_ssrc[s] + sd;
            float e = v > 0.f ? v : 0.01f * v;
            exv = __expf(e);
            w = (et == 0 ? 0.f : __ldg(&rel[et])) * exv;
        }
        dsum += exv;
        int cnt = min(32, end - base);
#pragma unroll 8
        for (int i = 0; i < cnt; i++) {
            float wi = __shfl_sync(0xffffffffu, w, i);
            int   si = __shfl_sync(0xffffffffu, s, i);
            float4 zv = z4[(size_t)si * 32 + lane];
            acc.x += wi * zv.x;
            acc.y += wi * zv.y;
            acc.z += wi * zv.z;
            acc.w += wi * zv.w;
        }
    }

#pragma unroll
    for (int o = 16; o > 0; o >>= 1)
        dsum += __shfl_xor_sync(0xffffffffu, dsum, o);

    float inv = dsum > 0.f ? __frcp_rn(dsum) : 0.f;
    float4* o4 = (float4*)out;
    o4[(size_t)node * 32 + lane] =
        make_float4(acc.x * inv, acc.y * inv, acc.z * inv, acc.w * inv);
}

// ---------------------------------------------------------------------------
extern "C" void kernel_launch(void* const* d_in, const int* in_sizes, int n_in,
                              void* d_out, int out_size) {
    const float* h    = (const float*)d_in[0];
    const float* W    = (const float*)d_in[1];
    const float* attn = (const float*)d_in[2];
    const float* rel  = (const float*)d_in[3];
    const int*   src  = (const int*)d_in[4];
    const int*   dst  = (const int*)d_in[5];
    const int*   et   = (const int*)d_in[6];
    float* out = (float*)d_out;

    int N = in_sizes[0] / DOUT;
    int E = in_sizes[4];
    int nblk = (N + CHUNK - 1) / CHUNK;

    cudaFuncSetAttribute(gemm_kernel, cudaFuncAttributeMaxDynamicSharedMemorySize, 96 * 1024);
    gemm_kernel<<<(N + 63) / 64, 256, 96 * 1024>>>(h, W, attn, N);

    hist_kernel<<<(E + 255) / 256, 256>>>(dst, E);
    scan_kernel<<<nblk, 256>>>(N);
    scatter_kernel<<<(E + 255) / 256, 256>>>(src, dst, et, E);

    gather_kernel<<<(N * 32 + 255) / 256, 256>>>(rel, out, N);
}

// round 5
// speedup vs baseline: 1.9204x; 1.0459x over previous
#include <cuda_runtime.h>
#include <cuda_fp16.h>

#define DOUT 128
#define N_MAX 50000
#define E_MAX 800000
#define CHUNK 4096

// Scratch (device globals — no allocation allowed)
__device__ __half g_zh[(size_t)N_MAX * DOUT];   // messages in fp16 (halved traffic)
__device__ float  g_ssrc[N_MAX];
__device__ float  g_sdst[N_MAX];
__device__ int    g_cnt[N_MAX];
__device__ int    g_off[N_MAX + 1];
__device__ int    g_rank[E_MAX];                // edge's rank within its dst segment
__device__ int    g_packed[E_MAX];              // src | (etype << 17)

// ---------------------------------------------------------------------------
// z = h @ W  (smem-tiled fp32), s_src = z@a_l, s_dst = z@a_r (fp32 scores),
// z stored to global as fp16. Also zeroes g_cnt as a side job.
// ---------------------------------------------------------------------------
__global__ void __launch_bounds__(256, 2)
gemm_kernel(const float* __restrict__ h, const float* __restrict__ W,
            const float* __restrict__ attn, int N) {
    extern __shared__ float smem[];
    float* Ws = smem;                 // [128][128]
    float* hs = smem + DOUT * DOUT;   // [64][128]

    int tid = threadIdx.x;

    // fused clear of g_cnt (grid*256 >= N)
    int ci = blockIdx.x * 256 + tid;
    if (ci < N) g_cnt[ci] = 0;

    const float4* W4 = (const float4*)W;
    float4* Ws4 = (float4*)Ws;
#pragma unroll
    for (int i = 0; i < 16; i++)
        Ws4[tid + i * 256] = W4[tid + i * 256];

    int rowbase = blockIdx.x * 64;
    float4* hs4 = (float4*)hs;
    const float4* h4 = (const float4*)h;
#pragma unroll
    for (int i = 0; i < 8; i++) {
        int idx = tid + i * 256;
        int r = idx >> 5;
        int c = idx & 31;
        float4 v = make_float4(0.f, 0.f, 0.f, 0.f);
        if (rowbase + r < N) v = h4[(size_t)(rowbase + r) * 32 + c];
        hs4[idx] = v;
    }
    __syncthreads();

    int warp = tid >> 5, lane = tid & 31;
    int r0 = warp * 8;

    float4 acc[8];
#pragma unroll
    for (int r = 0; r < 8; r++) acc[r] = make_float4(0.f, 0.f, 0.f, 0.f);

#pragma unroll 4
    for (int k = 0; k < DOUT; k++) {
        float4 wk = Ws4[k * 32 + lane];
#pragma unroll
        for (int r = 0; r < 8; r++) {
            float hv = hs[(r0 + r) * DOUT + k];
            acc[r].x += hv * wk.x;
            acc[r].y += hv * wk.y;
            acc[r].z += hv * wk.z;
            acc[r].w += hv * wk.w;
        }
    }

    float4 al = ((const float4*)attn)[lane];
    float4 ar = ((const float4*)attn)[32 + lane];
    uint2* zh2 = (uint2*)g_zh;   // 4 halves per lane slot, 32 slots per row
#pragma unroll
    for (int r = 0; r < 8; r++) {
        int row = rowbase + r0 + r;
        if (row >= N) break;
        __half2 lo = __floats2half2_rn(acc[r].x, acc[r].y);
        __half2 hi = __floats2half2_rn(acc[r].z, acc[r].w);
        uint2 pk;
        pk.x = *(unsigned*)&lo;
        pk.y = *(unsigned*)&hi;
        zh2[(size_t)row * 32 + lane] = pk;

        float ps = acc[r].x * al.x + acc[r].y * al.y + acc[r].z * al.z + acc[r].w * al.w;
        float pd = acc[r].x * ar.x + acc[r].y * ar.y + acc[r].z * ar.z + acc[r].w * ar.w;
#pragma unroll
        for (int o = 16; o > 0; o >>= 1) {
            ps += __shfl_xor_sync(0xffffffffu, ps, o);
            pd += __shfl_xor_sync(0xffffffffu, pd, o);
        }
        if (lane == 0) { g_ssrc[row] = ps; g_sdst[row] = pd; }
    }
}

// ---------------------------------------------------------------------------
// Histogram of dst; the atomic's return value IS the edge's rank — store it.
// ---------------------------------------------------------------------------
__global__ void hist_kernel(const int* __restrict__ dst, int E) {
    int i = blockIdx.x * blockDim.x + threadIdx.x;
    if (i < E) g_rank[i] = atomicAdd(&g_cnt[dst[i]], 1);
}

// ---------------------------------------------------------------------------
// Single-kernel exclusive scan: block b redundantly reduces [0, b*CHUNK),
// then scans its own CHUNK. No inter-block protocol.
// ---------------------------------------------------------------------------
__global__ void __launch_bounds__(256)
scan_kernel(int N) {
    __shared__ int sh[9];
    int b = blockIdx.x, t = threadIdx.x;
    int lane = t & 31, wid = t >> 5;
    int base = b * CHUNK;

    int pre = 0;
    const int4* c4 = (const int4*)g_cnt;
    for (int i = t; i * 4 < base; i += 256) {
        int4 v = c4[i];
        pre += v.x + v.y + v.z + v.w;
    }
#pragma unroll
    for (int o = 16; o > 0; o >>= 1) pre += __shfl_xor_sync(0xffffffffu, pre, o);
    if (lane == 0) sh[wid] = pre;
    __syncthreads();
    if (t == 0) {
        int s = 0;
#pragma unroll
        for (int i = 0; i < 8; i++) s += sh[i];
        sh[8] = s;
    }
    __syncthreads();
    int pretot = sh[8];
    __syncthreads();

    int tbase = base + t * 16;
    int vals[16];
    int tsum = 0;
    if (tbase + 16 <= N) {
#pragma unroll
        for (int j = 0; j < 16; j += 4) {
            int4 v = c4[(tbase + j) >> 2];
            vals[j] = v.x; vals[j+1] = v.y; vals[j+2] = v.z; vals[j+3] = v.w;
            tsum += v.x + v.y + v.z + v.w;
        }
    } else {
#pragma unroll
        for (int j = 0; j < 16; j++) {
            int idx = tbase + j;
            vals[j] = (idx < N) ? g_cnt[idx] : 0;
            tsum += vals[j];
        }
    }

    int x = tsum;
#pragma unroll
    for (int o = 1; o < 32; o <<= 1) {
        int y = __shfl_up_sync(0xffffffffu, x, o);
        if (lane >= o) x += y;
    }
    if (lane == 31) sh[wid] = x;
    __syncthreads();
    if (t < 8) {
        int s = sh[t];
#pragma unroll
        for (int o = 1; o < 8; o <<= 1) {
            int y = __shfl_up_sync(0x000000ffu, s, o);
            if (t >= o) s += y;
        }
        sh[t] = s;
    }
    __syncthreads();

    int run = pretot + (wid ? sh[wid - 1] : 0) + x - tsum;
#pragma unroll
    for (int j = 0; j < 16; j++) {
        int idx = tbase + j;
        if (idx < N) g_off[idx] = run;
        run += vals[j];
    }
    if (t == 0 && b == gridDim.x - 1) g_off[N] = pretot + sh[7];
}

// ---------------------------------------------------------------------------
// Atomic-free scatter: pos = off[dst] + rank (rank captured in hist).
// ---------------------------------------------------------------------------
__global__ void scatter_kernel(const int* __restrict__ src, const int* __restrict__ dst,
                               const int* __restrict__ etype, int E) {
    int i = blockIdx.x * blockDim.x + threadIdx.x;
    if (i >= E) return;
    int pos = g_off[dst[i]] + g_rank[i];
    g_packed[pos] = src[i] | (etype[i] << 17);
}

// ---------------------------------------------------------------------------
// One warp per dst node: fused softmax (no max shift — scores bounded,
// leaky_relu monotone) + fp16 message gather + normalize. No float atomics.
// ---------------------------------------------------------------------------
__global__ void __launch_bounds__(256)
gather_kernel(const float* __restrict__ rel, float* __restrict__ out, int N) {
    int node = (blockIdx.x * blockDim.x + threadIdx.x) >> 5;
    int lane = threadIdx.x & 31;
    if (node >= N) return;

    int beg = g_off[node], end = g_off[node + 1];
    float sd = g_sdst[node];

    float4 acc = make_float4(0.f, 0.f, 0.f, 0.f);
    float dsum = 0.f;
    const uint2* zh2 = (const uint2*)g_zh;

    for (int base = beg; base < end; base += 32) {
        int idx = base + lane;
        float w = 0.f, exv = 0.f;
        int s = 0;
        if (idx < end) {
            int p = g_packed[idx];
            s = p & 131071;
            int et = p >> 17;
            float v = g_ssrc[s] + sd;
            float e = v > 0.f ? v : 0.01f * v;
            exv = __expf(e);
            w = (et == 0 ? 0.f : __ldg(&rel[et])) * exv;
        }
        dsum += exv;
        int cnt = min(32, end - base);
#pragma unroll 8
        for (int i = 0; i < cnt; i++) {
            float wi = __shfl_sync(0xffffffffu, w, i);
            int   si = __shfl_sync(0xffffffffu, s, i);
            uint2 raw = zh2[(size_t)si * 32 + lane];
            float2 f01 = __half22float2(*(__half2*)&raw.x);
            float2 f23 = __half22float2(*(__half2*)&raw.y);
            acc.x += wi * f01.x;
            acc.y += wi * f01.y;
            acc.z += wi * f23.x;
            acc.w += wi * f23.y;
        }
    }

#pragma unroll
    for (int o = 16; o > 0; o >>= 1)
        dsum += __shfl_xor_sync(0xffffffffu, dsum, o);

    float inv = dsum > 0.f ? __frcp_rn(dsum) : 0.f;
    float4* o4 = (float4*)out;
    o4[(size_t)node * 32 + lane] =
        make_float4(acc.x * inv, acc.y * inv, acc.z * inv, acc.w * inv);
}

// ---------------------------------------------------------------------------
extern "C" void kernel_launch(void* const* d_in, const int* in_sizes, int n_in,
                              void* d_out, int out_size) {
    const float* h    = (const float*)d_in[0];
    const float* W    = (const float*)d_in[1];
    const float* attn = (const float*)d_in[2];
    const float* rel  = (const float*)d_in[3];
    const int*   src  = (const int*)d_in[4];
    const int*   dst  = (const int*)d_in[5];
    const int*   et   = (const int*)d_in[6];
    float* out = (float*)d_out;

    int N = in_sizes[0] / DOUT;
    int E = in_sizes[4];
    int nblk = (N + CHUNK - 1) / CHUNK;

    cudaFuncSetAttribute(gemm_kernel, cudaFuncAttributeMaxDynamicSharedMemorySize, 96 * 1024);
    gemm_kernel<<<(N + 63) / 64, 256, 96 * 1024>>>(h, W, attn, N);

    hist_kernel<<<(E + 255) / 256, 256>>>(dst, E);
    scan_kernel<<<nblk, 256>>>(N);
    scatter_kernel<<<(E + 255) / 256, 256>>>(src, dst, et, E);

    gather_kernel<<<(N * 32 + 255) / 256, 256>>>(rel, out, N);
}